// round 16
// baseline (speedup 1.0000x reference)
#include <cuda_runtime.h>
#include <cuda_fp16.h>
#include <cstdint>

// Problem sizes (fixed by dataset)
#define TOK    8192      // B*S
#define DDIM   1024
#define NPOOL  64
#define RDIM   128

// Static device scratch (no runtime alloc):
__device__ float    g_h[4u * TOK * RDIM];              // 4 n-quarter h partials (16MB)
__device__ uint32_t g_FKh[(size_t)NPOOL * 512 * 128];  // fp16-pair packed FK: [n][d/2][r] (16MB)
__device__ uint32_t g_RKh[(size_t)NPOOL * 64 * 1024];  // fp16-pair packed RK: [n][r/2][d] (16MB)

// ---------------- helpers ----------------
__device__ __forceinline__ uint32_t smem_u32(const void* p) {
    uint32_t a;
    asm("{ .reg .u64 t; cvta.to.shared.u64 t, %1; cvt.u32.u64 %0, t; }" : "=r"(a) : "l"(p));
    return a;
}
// pack two f32 -> f16x2 (lo in lower 16 bits)
__device__ __forceinline__ uint32_t pack_h2(float lo, float hi) {
    uint32_t u;
    asm("cvt.rn.f16x2.f32 %0, %1, %2;" : "=r"(u) : "f"(hi), "f"(lo));
    return u;
}
__device__ __forceinline__ void cp_async16(uint32_t smem_dst, const void* gptr) {
    asm volatile("cp.async.cg.shared.global [%0], [%1], 16;" :: "r"(smem_dst), "l"(gptr) : "memory");
}
#define MBARRIER_INIT(addr, cnt) \
    asm volatile("mbarrier.init.shared.b64 [%0], %1;" :: "r"((uint32_t)(addr)), "r"((uint32_t)(cnt)) : "memory")
#define MBARRIER_ARRIVE(addr) \
    asm volatile("mbarrier.arrive.shared.b64 _, [%0];" :: "r"((uint32_t)(addr)) : "memory")
// .noinc is load-bearing: default form is count-neutral; .noinc contributes to expected count.
#define CP_MBAR_ARRIVE(addr) \
    asm volatile("cp.async.mbarrier.arrive.noinc.shared.b64 [%0];" :: "r"((uint32_t)(addr)) : "memory")

#define MBARRIER_WAIT_PARITY(addr, par) do { \
    uint32_t _m = (uint32_t)(addr), _p = (uint32_t)(par), _d; \
    asm volatile("{ .reg .pred p; mbarrier.try_wait.parity.acquire.cta.shared::cta.b64 p, [%1], %2; selp.b32 %0,1,0,p; }" \
        : "=r"(_d) : "r"(_m), "r"(_p) : "memory"); \
    if (!_d) { \
        asm volatile("{ .reg .pred P1; WL_%=: mbarrier.try_wait.parity.acquire.cta.shared::cta.b64 P1, [%0], %1, 0x989680; @P1 bra.uni WD_%=; bra.uni WL_%=; WD_%=: }" \
            :: "r"(_m), "r"(_p) : "memory"); \
    } } while (0)

// fp16 MMA: m16n8k16, f32 accumulate
__device__ __forceinline__ void mma_f16(float* c, const uint32_t* a, uint32_t b0, uint32_t b1) {
    asm volatile(
        "mma.sync.aligned.m16n8k16.row.col.f32.f16.f16.f32 "
        "{%0,%1,%2,%3}, {%4,%5,%6,%7}, {%8,%9}, {%0,%1,%2,%3};"
        : "+f"(c[0]), "+f"(c[1]), "+f"(c[2]), "+f"(c[3])
        : "r"(a[0]), "r"(a[1]), "r"(a[2]), "r"(a[3]), "r"(b0), "r"(b1));
}

// Swizzled SMEM indexing in uint32 (=f16x2 pair) units. kp = k/2 (pair index, 0..31).
// A: [m][kp], rows x 32 ;  B: [kp][n], 32 x NC
#define AIDX(m, kp) ((m) * 32 + ((kp) ^ (((m) & 7) << 2)))
template<int NC>
__device__ __forceinline__ int bidx(int kp, int n) { return (kp) * NC + ((n) ^ (((kp) & 3) << 3)); }

// SMEM: [0..1023] barriers (256 u32); then NST stages x 12288 u32 (48KB):
//   stage1: A 8192 u32 (256m x 32kp), B 4096 u32 (32kp x 128n)
//   stage2: A 4096 u32 (128m x 32kp), B 8192 u32 (32kp x 256n)
#define NST 3
#define SM_BASE(s) (256 + (s) * 12288)
#define SMEM_BYTES ((256 + NST * 12288) * 4)
// barrier byte offsets: full[s] = s*8 ; empty[s] = 64 + s*8

// ---------------- consumer compute core: 64x64 warp tile, K=64 halfs (32 kp) ----------------
struct Frag { float c[4][8][4]; };   // 128 accum regs

template<int NC>
__device__ __forceinline__ void compute64(const uint32_t* __restrict__ As,
                                          const uint32_t* __restrict__ Bs,
                                          int rA, int ncol, int cA, int nB, int kB, Frag& F) {
    #pragma unroll
    for (int ks = 0; ks < 4; ++ks) {        // 4 x K16 mma steps
        int kp0 = ks * 8;
        uint32_t a[4][4];
        #pragma unroll
        for (int mt = 0; mt < 4; ++mt) {
            int m = rA + mt * 16;
            a[mt][0] = As[AIDX(m,     kp0 + cA)];
            a[mt][1] = As[AIDX(m + 8, kp0 + cA)];
            a[mt][2] = As[AIDX(m,     kp0 + 4 + cA)];
            a[mt][3] = As[AIDX(m + 8, kp0 + 4 + cA)];
        }
        #pragma unroll
        for (int np = 0; np < 4; ++np) {     // nt pairs: 4 live b regs
            uint32_t b[2][2];
            #pragma unroll
            for (int j = 0; j < 2; ++j) {
                int n = ncol + (np * 2 + j) * 8 + nB;
                b[j][0] = Bs[bidx<NC>(kp0 + kB,     n)];
                b[j][1] = Bs[bidx<NC>(kp0 + 4 + kB, n)];
            }
            #pragma unroll
            for (int j = 0; j < 2; ++j)
                #pragma unroll
                for (int mt = 0; mt < 4; ++mt)
                    mma_f16(F.c[mt][np * 2 + j], a[mt], b[j][0], b[j][1]);
        }
    }
}

__device__ __forceinline__ void zero_frag(Frag& F) {
    #pragma unroll
    for (int mt = 0; mt < 4; ++mt)
        #pragma unroll
        for (int nt = 0; nt < 8; ++nt)
            #pragma unroll
            for (int q = 0; q < 4; ++q) F.c[mt][nt][q] = 0.f;
}

// ==================== one-shot converters ====================
__global__ void cvt_fk(const float* __restrict__ FK) {
    int gid = blockIdx.x * 256 + threadIdx.x;      // 0 .. 64*512*128-1
    int n = gid >> 16, rem = gid & 65535;
    int dp = rem >> 7, r = rem & 127;
    const float* s = &FK[((size_t)n * DDIM + 2 * dp) * RDIM + r];
    g_FKh[gid] = pack_h2(s[0], s[RDIM]);
}
__global__ void cvt_rk(const float* __restrict__ RK) {
    int gid = blockIdx.x * 256 + threadIdx.x;      // 0 .. 64*64*1024-1
    int n = gid >> 16, rem = gid & 65535;
    int rp = rem >> 10, d = rem & 1023;
    const float* s = &RK[((size_t)n * RDIM + 2 * rp) * DDIM + d];
    g_RKh[gid] = pack_h2(s[0], s[DDIM]);
}

// ==================== Stage 1 ====================
// grid (32 token-tiles of 256, 4 n-quarters). C[256 tok,128 r], K = 16n x 1024d.
// chunk c: dblock = c>>3 (32 d), npair = c&7 -> n = n0 + 2*(c&7). CHUNKS=256.
__global__ __launch_bounds__(384, 1)
void kc_stage1(const float* __restrict__ x, const float* __restrict__ fw) {
    extern __shared__ uint32_t smem[];
    uint32_t sb = smem_u32(smem);
    int tid = threadIdx.x, wid = tid >> 5, lane = tid & 31;
    int tok0 = blockIdx.x * 256;
    int n0 = blockIdx.y * 16;
    const int CHUNKS = 32 * 8;  // 256

    if (tid == 0) {
        #pragma unroll
        for (int s = 0; s < NST; ++s) {
            MBARRIER_INIT(sb + s * 8, 256);       // full: 128 STS-arrives + 128 cp-noinc
            MBARRIER_INIT(sb + 64 + s * 8, 256);  // empty: 256 consumer threads
        }
    }
    __syncthreads();

    if (wid >= 8) {
        // ---------------- producer (4 warps, 128 threads) ----------------
        int pt = tid - 256;           // 0..127
        int rbase = pt & 15;          // rows rbase + 16*p, p=0..15
        int g8 = pt >> 4;             // 0..7
        int nh = g8 >> 2;             // n-half (0/1)
        int d8 = (g8 & 3) * 8;        // 8 d within 32-d block
        int kp4 = nh * 16 + (g8 & 3) * 4;
        float4 xc[16][2];
        int st = 0, ph = 1;
        for (int c = 0; c < CHUNKS; ++c) {
            int d0 = (c >> 3) * 32;
            int n = n0 + 2 * (c & 7);
            int nn = n + nh;
            if ((c & 7) == 0) {       // refresh x cache per d-block
                #pragma unroll
                for (int p = 0; p < 16; ++p) {
                    const float* xp = &x[(size_t)(tok0 + rbase + 16 * p) * DDIM + d0 + d8];
                    xc[p][0] = *(const float4*)&xp[0];
                    xc[p][1] = *(const float4*)&xp[4];
                }
            }
            MBARRIER_WAIT_PARITY(sb + 64 + st * 8, ph);
            uint32_t* A = smem + SM_BASE(st);
            #pragma unroll
            for (int p = 0; p < 16; ++p) {
                int m = rbase + 16 * p;
                float w = fw[(tok0 + m) * NPOOL + nn];
                uint4 t4;
                t4.x = pack_h2(xc[p][0].x * w, xc[p][0].y * w);
                t4.y = pack_h2(xc[p][0].z * w, xc[p][0].w * w);
                t4.z = pack_h2(xc[p][1].x * w, xc[p][1].y * w);
                t4.w = pack_h2(xc[p][1].z * w, xc[p][1].w * w);
                *(uint4*)&A[AIDX(m, kp4)] = t4;
            }
            MBARRIER_ARRIVE(sb + st * 8);
            // B via cp.async from pre-packed FKh: [n][dp][r]
            uint32_t bb = sb + 4u * (SM_BASE(st) + 8192);
            int dp0 = (c >> 3) * 16;
            #pragma unroll
            for (int it = 0; it < 8; ++it) {
                int G = pt + it * 128;             // 0..1023
                int kp = G >> 5, g = G & 31;
                int bn = n + (kp >> 4);
                const uint32_t* src = &g_FKh[((size_t)bn * 512 + dp0 + (kp & 15)) * 128 + g * 4];
                cp_async16(bb + 4u * bidx<128>(kp, g * 4), src);
            }
            CP_MBAR_ARRIVE(sb + st * 8);
            if (++st == NST) { st = 0; ph ^= 1; }
        }
        return;
    }

    // ---------------- consumers (8 warps, 64x64: 4 row-bands x 2 col-bands) ----------------
    int mb = wid & 3, nb = wid >> 2;
    int rA = mb * 64 + (lane >> 2);
    int ncol = nb * 64;
    int cA = lane & 3, nB = lane >> 2, kB = lane & 3;
    Frag F;
    zero_frag(F);
    {
        int st = 0, ph = 0;
        for (int c = 0; c < CHUNKS; ++c) {
            MBARRIER_WAIT_PARITY(sb + st * 8, ph);
            compute64<128>(smem + SM_BASE(st), smem + SM_BASE(st) + 8192, rA, ncol, cA, nB, kB, F);
            MBARRIER_ARRIVE(sb + 64 + st * 8);
            if (++st == NST) { st = 0; ph ^= 1; }
        }
    }
    // epilogue: write h partial
    {
        size_t hb = (size_t)blockIdx.y * TOK;
        #pragma unroll
        for (int mt = 0; mt < 4; ++mt) {
            int row = tok0 + mb * 64 + mt * 16 + (lane >> 2);
            #pragma unroll
            for (int nt = 0; nt < 8; ++nt) {
                int col = ncol + nt * 8 + (lane & 3) * 2;
                *(float2*)&g_h[(hb + row) * RDIM + col]     = make_float2(F.c[mt][nt][0], F.c[mt][nt][1]);
                *(float2*)&g_h[(hb + row + 8) * RDIM + col] = make_float2(F.c[mt][nt][2], F.c[mt][nt][3]);
            }
        }
    }
}

// ==================== Stage 2 ====================
// grid (64 token-tiles of 128, 4 d-tiles of 256). K = 64n x 128r.
// chunk c: rblock = c>>5 (32 r), npair = c&31 -> n = 2*(c&31). CHUNKS=128.
__global__ __launch_bounds__(384, 1)
void kc_stage2(const float* __restrict__ rw, float* __restrict__ out) {
    extern __shared__ uint32_t smem[];
    uint32_t sb = smem_u32(smem);
    int tid = threadIdx.x, wid = tid >> 5, lane = tid & 31;
    int tok0 = blockIdx.x * 128;
    int dt0 = blockIdx.y * 256;
    const int CHUNKS = 4 * 32;  // 128

    if (tid == 0) {
        #pragma unroll
        for (int s = 0; s < NST; ++s) {
            MBARRIER_INIT(sb + s * 8, 256);
            MBARRIER_INIT(sb + 64 + s * 8, 256);
        }
    }
    __syncthreads();

    if (wid >= 8) {
        // ---------------- producer ----------------
        int pt = tid - 256;
        int rbase = pt & 15;          // rows rbase + 16*p, p=0..7
        int g8 = pt >> 4;
        int nh = g8 >> 2;
        int r8 = (g8 & 3) * 8;
        int kp4 = nh * 16 + (g8 & 3) * 4;
        float4 hc[8][2];
        int st = 0, ph = 1;
        for (int c = 0; c < CHUNKS; ++c) {
            int r0 = (c >> 5) * 32;
            int n = 2 * (c & 31);
            int nn = n + nh;
            if ((c & 31) == 0) {      // refresh summed-h cache per r-block
                #pragma unroll
                for (int p = 0; p < 8; ++p) {
                    size_t ho = (size_t)(tok0 + rbase + 16 * p) * RDIM + r0 + r8;
                    #pragma unroll
                    for (int j = 0; j < 2; ++j) {
                        float4 v0 = *(const float4*)&g_h[ho + j * 4];
                        float4 v1 = *(const float4*)&g_h[1u * TOK * RDIM + ho + j * 4];
                        float4 v2 = *(const float4*)&g_h[2u * TOK * RDIM + ho + j * 4];
                        float4 v3 = *(const float4*)&g_h[3u * TOK * RDIM + ho + j * 4];
                        hc[p][j] = make_float4((v0.x + v1.x) + (v2.x + v3.x),
                                               (v0.y + v1.y) + (v2.y + v3.y),
                                               (v0.z + v1.z) + (v2.z + v3.z),
                                               (v0.w + v1.w) + (v2.w + v3.w));
                    }
                }
            }
            MBARRIER_WAIT_PARITY(sb + 64 + st * 8, ph);
            uint32_t* A = smem + SM_BASE(st);
            #pragma unroll
            for (int p = 0; p < 8; ++p) {
                int m = rbase + 16 * p;
                float w = rw[(tok0 + m) * NPOOL + nn];
                uint4 t4;
                t4.x = pack_h2(hc[p][0].x * w, hc[p][0].y * w);
                t4.y = pack_h2(hc[p][0].z * w, hc[p][0].w * w);
                t4.z = pack_h2(hc[p][1].x * w, hc[p][1].y * w);
                t4.w = pack_h2(hc[p][1].z * w, hc[p][1].w * w);
                *(uint4*)&A[AIDX(m, kp4)] = t4;
            }
            MBARRIER_ARRIVE(sb + st * 8);
            // B via cp.async from pre-packed RKh: [n][rp][d]
            uint32_t bb = sb + 4u * (SM_BASE(st) + 4096);
            int rp0 = (c >> 5) * 16;
            #pragma unroll
            for (int it = 0; it < 16; ++it) {
                int G = pt + it * 128;             // 0..2047
                int kp = G >> 6, g = G & 63;
                int bn = n + (kp >> 4);
                const uint32_t* src = &g_RKh[((size_t)bn * 64 + rp0 + (kp & 15)) * 1024 + dt0 + g * 4];
                cp_async16(bb + 4u * bidx<256>(kp, g * 4), src);
            }
            CP_MBAR_ARRIVE(sb + st * 8);
            if (++st == NST) { st = 0; ph ^= 1; }
        }
        return;
    }

    // ---------------- consumers (8 warps, 64x64: 2 row-bands x 4 col-bands) ----------------
    int mb = wid & 1, nb = wid >> 1;
    int rA = mb * 64 + (lane >> 2);
    int ncol = nb * 64;
    int cA = lane & 3, nB = lane >> 2, kB = lane & 3;
    Frag F;
    zero_frag(F);
    {
        int st = 0, ph = 0;
        for (int c = 0; c < CHUNKS; ++c) {
            MBARRIER_WAIT_PARITY(sb + st * 8, ph);
            compute64<256>(smem + SM_BASE(st), smem + SM_BASE(st) + 4096, rA, ncol, cA, nB, kB, F);
            MBARRIER_ARRIVE(sb + 64 + st * 8);
            if (++st == NST) { st = 0; ph ^= 1; }
        }
    }
    // epilogue: write out
    {
        #pragma unroll
        for (int mt = 0; mt < 4; ++mt) {
            int row = tok0 + mb * 64 + mt * 16 + (lane >> 2);
            #pragma unroll
            for (int nt = 0; nt < 8; ++nt) {
                int col = dt0 + nb * 64 + nt * 8 + (lane & 3) * 2;
                *(float2*)&out[(size_t)row * DDIM + col]       = make_float2(F.c[mt][nt][0], F.c[mt][nt][1]);
                *(float2*)&out[(size_t)(row + 8) * DDIM + col] = make_float2(F.c[mt][nt][2], F.c[mt][nt][3]);
            }
        }
    }
}

// ==================== launch ====================
extern "C" void kernel_launch(void* const* d_in, const int* in_sizes, int n_in,
                              void* d_out, int out_size) {
    const float* x  = (const float*)d_in[0];
    const float* fw = (const float*)d_in[1];
    const float* rw = (const float*)d_in[2];
    const float* FK = (const float*)d_in[3];
    const float* RK = (const float*)d_in[4];
    float* out = (float*)d_out;

    cudaFuncSetAttribute(kc_stage1, cudaFuncAttributeMaxDynamicSharedMemorySize, SMEM_BYTES);
    cudaFuncSetAttribute(kc_stage2, cudaFuncAttributeMaxDynamicSharedMemorySize, SMEM_BYTES);

    cvt_fk<<<(NPOOL * 512 * 128) / 256, 256>>>(FK);
    cvt_rk<<<(NPOOL * 64 * 1024) / 256, 256>>>(RK);
    kc_stage1<<<dim3(32, 4), 384, SMEM_BYTES>>>(x, fw);
    kc_stage2<<<dim3(64, 4), 384, SMEM_BYTES>>>(rw, out);
}